// round 5
// baseline (speedup 1.0000x reference)
#include <cuda_runtime.h>

#define Bv 8
#define Nv 128
#define Tv 256
#define Lv 32
#define Hv 128
#define TTv 224   // T - L

// Scratch (static device globals; allocation-free)
__device__ float g_wsum8[8 * Nv * Hv];     // partial sum_j W_fc[n,j,h] (8 j-slabs)
__device__ float g_bsum[Nv];               // sum_j b_fc[n,j]
__device__ float g_hsum[Bv * Nv * Hv];     // sum_t h[b,n,t,h]/x[b,n,t+L]
__device__ float g_R[Bv * Nv];             // sum_t 1/x[b,n,t+L]

typedef unsigned long long u64t;

__device__ __forceinline__ u64t ffma2(u64t a, u64t b, u64t c) {
    u64t d;
    asm("fma.rn.f32x2 %0, %1, %2, %3;" : "=l"(d) : "l"(a), "l"(b), "l"(c));
    return d;
}
__device__ __forceinline__ u64t pack2(float lo, float hi) {
    u64t u;
    asm("mov.b64 %0, {%1, %2};" : "=l"(u) : "f"(lo), "f"(hi));
    return u;
}
__device__ __forceinline__ float2 unpack2(u64t u) {
    float2 r;
    asm("mov.b64 {%0, %1}, %2;" : "=f"(r.x), "=f"(r.y) : "l"(u));
    return r;
}
__device__ __forceinline__ float tanh_fast(float v) {
    float r;
    asm("tanh.approx.f32 %0, %1;" : "=f"(r) : "f"(v));
    return r;
}
__device__ __forceinline__ float sig_fast(float v) {
    return fmaf(0.5f, tanh_fast(0.5f * v), 0.5f);
}

// ---------------------------------------------------------------------------
// K0: partial Wsum[n,h] over 8 j-slabs; float4 loads, 2-level reduce. bsum[n].
// Block (n, jc): 128 thr = 4 j-groups x 32 lanes (lane = h-quad).
// ---------------------------------------------------------------------------
__global__ void __launch_bounds__(128) k_prep(const float* __restrict__ Wfc,
                                              const float* __restrict__ bfc) {
    const int n = blockIdx.x, jc = blockIdx.y;
    const int tid = threadIdx.x;
    const int lane = tid & 31, jg = tid >> 5;
    __shared__ float4 part[4][32];

    const float* base = Wfc + (size_t)n * Nv * Hv + (size_t)(jc * 16 + jg * 4) * Hv;
    float4 s = make_float4(0.f, 0.f, 0.f, 0.f);
#pragma unroll
    for (int jj = 0; jj < 4; jj++) {
        const float4 v = ((const float4*)(base + (size_t)jj * Hv))[lane];
        s.x += v.x; s.y += v.y; s.z += v.z; s.w += v.w;
    }
    part[jg][lane] = s;
    __syncthreads();
    if (jg == 0) {
        float4 a = part[0][lane], b2 = part[1][lane], c = part[2][lane], d = part[3][lane];
        a.x += b2.x + c.x + d.x; a.y += b2.y + c.y + d.y;
        a.z += b2.z + c.z + d.z; a.w += b2.w + c.w + d.w;
        ((float4*)(g_wsum8 + (size_t)(jc * Nv + n) * Hv))[lane] = a;
    }

    if (jc == 0) {
        float bvv = bfc[n * Nv + tid];
#pragma unroll
        for (int off = 16; off; off >>= 1) bvv += __shfl_xor_sync(0xffffffffu, bvv, off);
        __shared__ float red[4];
        if (lane == 0) red[jg] = bvv;
        __syncthreads();
        if (tid == 0) g_bsum[n] = red[0] + red[1] + red[2] + red[3];
    }
}

// ---------------------------------------------------------------------------
// K1: gates -> h ; accumulates Hsum, R ; X_hat via per-warp smem partials.
// Block (n,b), 128 threads = one h each. 8-t blocks, FFMA2 paired over t.
// Gates i,g weights in registers; gate-o weights pre-packed (w,w) in SMEM
// (cuts regs ~160 -> ~118 so the (128,4) occupancy cap below can bind).
// NO barriers inside the t-loop.
// ---------------------------------------------------------------------------
__global__ void __launch_bounds__(128, 4) k_lstm(const float* __restrict__ x,
                                                 const float* __restrict__ Wih,
                                                 const float* __restrict__ bih,
                                                 const float* __restrict__ bhh,
                                                 float* __restrict__ outX) {
    __shared__ __align__(16) float xs[Tv];
    __shared__ float2 po[128];            // odd-aligned pairs (x[2k+1], x[2k+2])
    __shared__ float rxs[TTv];
    __shared__ float redX[4 * TTv];       // per-warp X_hat partials
    __shared__ u64t  Wo2[Lv * 128];       // gate-o weights packed (w,w), 32 KB
    __shared__ float redR[4];

    const int n = blockIdx.x, b = blockIdx.y;
    const int tid = threadIdx.x;
    const int h = tid, lane = tid & 31, warp = tid >> 5;

    const float* xrow = x + ((size_t)b * Nv + n) * Tv;
    xs[tid] = xrow[tid];
    xs[tid + 128] = xrow[tid + 128];
    __syncthreads();

    if (tid < 127) po[tid] = make_float2(xs[2 * tid + 1], xs[2 * tid + 2]);
    for (int i = tid; i < TTv; i += 128) rxs[i] = 1.0f / xs[i + Lv];

    // Weights: gates {i, g} into registers; gate {o} packed into smem.
    float wi[Lv], wg[Lv];
    {
        const float* Wn = Wih + (size_t)n * 4 * Hv * Lv;
        const float4* p0 = (const float4*)(Wn + ((size_t)0 * Hv + h) * Lv);
        const float4* p2 = (const float4*)(Wn + ((size_t)2 * Hv + h) * Lv);
        const float4* p3 = (const float4*)(Wn + ((size_t)3 * Hv + h) * Lv);
#pragma unroll
        for (int q = 0; q < 8; q++) {
            float4 v0 = p0[q], v2 = p2[q], v3 = p3[q];
            wi[4 * q] = v0.x; wi[4 * q + 1] = v0.y; wi[4 * q + 2] = v0.z; wi[4 * q + 3] = v0.w;
            wg[4 * q] = v2.x; wg[4 * q + 1] = v2.y; wg[4 * q + 2] = v2.z; wg[4 * q + 3] = v2.w;
            Wo2[(4 * q + 0) * 128 + h] = pack2(v3.x, v3.x);
            Wo2[(4 * q + 1) * 128 + h] = pack2(v3.y, v3.y);
            Wo2[(4 * q + 2) * 128 + h] = pack2(v3.z, v3.z);
            Wo2[(4 * q + 3) * 128 + h] = pack2(v3.w, v3.w);
        }
    }

    const size_t bb4 = (size_t)n * 4 * Hv;
    const float bi = bih[bb4 + h]          + bhh[bb4 + h];
    const float bg = bih[bb4 + 2 * Hv + h] + bhh[bb4 + 2 * Hv + h];
    const float bo = bih[bb4 + 3 * Hv + h] + bhh[bb4 + 3 * Hv + h];
    const int nh = n * Hv + h;
    float wsum_h = 0.f;
#pragma unroll
    for (int s = 0; s < 8; s++) wsum_h += g_wsum8[s * Nv * Hv + nh];
    const float bsum_n = g_bsum[n];
    __syncthreads();

    // R[b,n] = sum_t rxs[t]
    {
        float r = 0.f;
        for (int i = tid; i < TTv; i += 128) r += rxs[i];
#pragma unroll
        for (int off = 16; off; off >>= 1) r += __shfl_xor_sync(0xffffffffu, r, off);
        if (lane == 0) redR[warp] = r;
        __syncthreads();
        if (tid == 0) g_R[b * Nv + n] = redR[0] + redR[1] + redR[2] + redR[3];
    }

    const u64t bi2 = pack2(bi, bi);
    const u64t bg2 = pack2(bg, bg);
    const u64t bo2 = pack2(bo, bo);

    float hs_acc = 0.f;

    for (int it = 0; it < TTv / 8; it++) {
        const int t0 = it * 8;     // even
        u64t ai[4], ag[4], ao[4];
#pragma unroll
        for (int p = 0; p < 4; p++) { ai[p] = bi2; ag[p] = bg2; ao[p] = bo2; }

        const u64t* peb = (const u64t*)xs + (t0 >> 1);   // even-aligned pairs
        const u64t* pob = (const u64t*)po + (t0 >> 1);   // odd-aligned pairs

#pragma unroll
        for (int l = 0; l < Lv; l++) {
            const u64t* px = (l & 1) ? (pob + ((l - 1) >> 1)) : (peb + (l >> 1));
            const u64t x0 = px[0], x1 = px[1], x2 = px[2], x3 = px[3];
            const u64t wi2 = pack2(wi[l], wi[l]);
            const u64t wg2 = pack2(wg[l], wg[l]);
            const u64t wo2 = Wo2[l * 128 + h];
            ai[0] = ffma2(x0, wi2, ai[0]); ai[1] = ffma2(x1, wi2, ai[1]);
            ai[2] = ffma2(x2, wi2, ai[2]); ai[3] = ffma2(x3, wi2, ai[3]);
            ag[0] = ffma2(x0, wg2, ag[0]); ag[1] = ffma2(x1, wg2, ag[1]);
            ag[2] = ffma2(x2, wg2, ag[2]); ag[3] = ffma2(x3, wg2, ag[3]);
            ao[0] = ffma2(x0, wo2, ao[0]); ao[1] = ffma2(x1, wo2, ao[1]);
            ao[2] = ffma2(x2, wo2, ao[2]); ao[3] = ffma2(x3, wo2, ao[3]);
        }

        float sx[8];
#pragma unroll
        for (int p = 0; p < 4; p++) {
            const float2 vi = unpack2(ai[p]);
            const float2 vg = unpack2(ag[p]);
            const float2 vo = unpack2(ao[p]);
            {
                const float c  = sig_fast(vi.x) * tanh_fast(vg.x);
                const float hv = sig_fast(vo.x) * tanh_fast(c);
                hs_acc = fmaf(hv, rxs[t0 + 2 * p], hs_acc);
                sx[2 * p] = hv * wsum_h;
            }
            {
                const float c  = sig_fast(vi.y) * tanh_fast(vg.y);
                const float hv = sig_fast(vo.y) * tanh_fast(c);
                hs_acc = fmaf(hv, rxs[t0 + 2 * p + 1], hs_acc);
                sx[2 * p + 1] = hv * wsum_h;
            }
        }

        // Warp-local reduce over h; lane0 stores per-warp partial. NO barrier.
#pragma unroll
        for (int tt = 0; tt < 8; tt++) {
            float v = sx[tt];
            v += __shfl_xor_sync(0xffffffffu, v, 16);
            v += __shfl_xor_sync(0xffffffffu, v, 8);
            v += __shfl_xor_sync(0xffffffffu, v, 4);
            v += __shfl_xor_sync(0xffffffffu, v, 2);
            v += __shfl_xor_sync(0xffffffffu, v, 1);
            if (lane == 0) redX[warp * TTv + t0 + tt] = v;
        }
    }

    g_hsum[((size_t)b * Nv + n) * Hv + h] = hs_acc;

    // Single barrier, then X_hat epilogue: sum 4 warp partials per t.
    __syncthreads();
    for (int i = tid; i < TTv; i += 128) {
        const float s = redX[i] + redX[TTv + i] + redX[2 * TTv + i] + redX[3 * TTv + i];
        outX[((size_t)b * TTv + i) * Nv + n] = s + bsum_n + 1e-6f;
    }
}

// ---------------------------------------------------------------------------
// K2: G[b,j,n] = (sum_h W_fc[n,j,h]*Hsum[b,n,h] + b_fc[n,j]*R[b,n]) / 224
// ---------------------------------------------------------------------------
__global__ void __launch_bounds__(256) k_gout(const float* __restrict__ Wfc,
                                              const float* __restrict__ bfc,
                                              float* __restrict__ outG) {
    const int n = blockIdx.x;
    const int tid = threadIdx.x;
    const int w = tid >> 5, lane = tid & 31;
    __shared__ __align__(16) float Hs[Bv][Hv];
    __shared__ float Rs[Bv];

    for (int i = tid; i < Bv * Hv; i += 256) {
        int bb = i >> 7, hh = i & 127;
        Hs[bb][hh] = g_hsum[((size_t)bb * Nv + n) * Hv + hh];
    }
    if (tid < Bv) Rs[tid] = g_R[tid * Nv + n];
    __syncthreads();

    float Hl[Bv][4];
#pragma unroll
    for (int bb = 0; bb < Bv; bb++) {
        float4 v = *(const float4*)&Hs[bb][4 * lane];
        Hl[bb][0] = v.x; Hl[bb][1] = v.y; Hl[bb][2] = v.z; Hl[bb][3] = v.w;
    }

    const float sc = 1.0f / (float)TTv;
#pragma unroll 2
    for (int jj = 0; jj < 16; jj++) {
        const int j = w * 16 + jj;
        const float4 wv = ((const float4*)(Wfc + ((size_t)n * Nv + j) * Hv))[lane];
        float acc[Bv];
#pragma unroll
        for (int bb = 0; bb < Bv; bb++) {
            acc[bb] = wv.x * Hl[bb][0] + wv.y * Hl[bb][1] +
                      wv.z * Hl[bb][2] + wv.w * Hl[bb][3];
        }
#pragma unroll
        for (int off = 16; off; off >>= 1) {
#pragma unroll
            for (int bb = 0; bb < Bv; bb++)
                acc[bb] += __shfl_xor_sync(0xffffffffu, acc[bb], off);
        }
        if (lane == 0) {
            const float bj = bfc[n * Nv + j];
#pragma unroll
            for (int bb = 0; bb < Bv; bb++)
                outG[((size_t)bb * Nv + j) * Nv + n] = (acc[bb] + bj * Rs[bb]) * sc;
        }
    }
}

// ---------------------------------------------------------------------------
extern "C" void kernel_launch(void* const* d_in, const int* in_sizes, int n_in,
                              void* d_out, int out_size) {
    (void)in_sizes; (void)n_in; (void)out_size;
    const float* x   = (const float*)d_in[0];
    const float* Wih = (const float*)d_in[1];
    const float* bih = (const float*)d_in[2];
    const float* bhh = (const float*)d_in[3];
    const float* Wfc = (const float*)d_in[4];
    const float* bfc = (const float*)d_in[5];

    float* outG = (float*)d_out;                       // (B, N, N)
    float* outX = outG + (size_t)Bv * Nv * Nv;         // (B, Ttau, N)

    dim3 g0(Nv, 8);
    k_prep<<<g0, 128>>>(Wfc, bfc);
    dim3 g1(Nv, Bv);
    k_lstm<<<g1, 128>>>(x, Wih, bih, bhh, outX);
    k_gout<<<Nv, 256>>>(Wfc, bfc, outG);
}

// round 6
// speedup vs baseline: 1.1925x; 1.1925x over previous
#include <cuda_runtime.h>

#define Bv 8
#define Nv 128
#define Tv 256
#define Lv 32
#define Hv 128
#define TTv 224   // T - L

// Scratch (static device globals; allocation-free)
__device__ float g_wsum4[4 * Nv * Hv];     // partial sum_j W_fc[n,j,h] (4 j-slabs)
__device__ float g_bsum[Nv];               // sum_j b_fc[n,j]
__device__ float g_hsum[Bv * Nv * Hv];     // sum_t h[b,n,t,h]/x[b,n,t+L]
__device__ float g_R[Bv * Nv];             // sum_t 1/x[b,n,t+L]

typedef unsigned long long u64t;

__device__ __forceinline__ u64t ffma2(u64t a, u64t b, u64t c) {
    u64t d;
    asm("fma.rn.f32x2 %0, %1, %2, %3;" : "=l"(d) : "l"(a), "l"(b), "l"(c));
    return d;
}
__device__ __forceinline__ u64t pack2(float lo, float hi) {
    u64t u;
    asm("mov.b64 %0, {%1, %2};" : "=l"(u) : "f"(lo), "f"(hi));
    return u;
}
__device__ __forceinline__ float2 unpack2(u64t u) {
    float2 r;
    asm("mov.b64 {%0, %1}, %2;" : "=f"(r.x), "=f"(r.y) : "l"(u));
    return r;
}
__device__ __forceinline__ float tanh_fast(float v) {
    float r;
    asm("tanh.approx.f32 %0, %1;" : "=f"(r) : "f"(v));
    return r;
}
__device__ __forceinline__ float sig_fast(float v) {
    return fmaf(0.5f, tanh_fast(0.5f * v), 0.5f);
}

// ---------------------------------------------------------------------------
// K0: partial Wsum[n,h] over 4 j-slabs; bsum[n]  (identical to the 141us R2)
// ---------------------------------------------------------------------------
__global__ void __launch_bounds__(128) k_prep(const float* __restrict__ Wfc,
                                              const float* __restrict__ bfc) {
    const int n = blockIdx.x, jc = blockIdx.y, h = threadIdx.x;
    const float* p = Wfc + (size_t)n * Nv * Hv + (size_t)jc * 32 * Hv + h;
    float s = 0.f;
#pragma unroll
    for (int j = 0; j < 32; j++) s += p[(size_t)j * Hv];
    g_wsum4[(jc * Nv + n) * Hv + h] = s;

    if (jc == 0) {
        float bvv = bfc[n * Nv + h];
#pragma unroll
        for (int off = 16; off; off >>= 1) bvv += __shfl_xor_sync(0xffffffffu, bvv, off);
        __shared__ float red[4];
        if ((h & 31) == 0) red[h >> 5] = bvv;
        __syncthreads();
        if (h == 0) g_bsum[n] = red[0] + red[1] + red[2] + red[3];
    }
}

// ---------------------------------------------------------------------------
// K1: R2 structure (ALL weights in registers, t-pair FFMA2) with ONE change:
// barrier-free X_hat — per-warp partials in smem, single barrier at the end.
// ---------------------------------------------------------------------------
__global__ void __launch_bounds__(128) k_lstm(const float* __restrict__ x,
                                              const float* __restrict__ Wih,
                                              const float* __restrict__ bih,
                                              const float* __restrict__ bhh,
                                              float* __restrict__ outX) {
    __shared__ __align__(16) float xs[Tv];
    __shared__ float2 po[127];            // odd-aligned pairs (x[2k+1], x[2k+2])
    __shared__ float rxs[TTv];
    __shared__ float redX[4 * TTv];       // per-warp X_hat partials
    __shared__ float redR[4];

    const int n = blockIdx.x, b = blockIdx.y;
    const int tid = threadIdx.x;
    const int h = tid, lane = tid & 31, warp = tid >> 5;

    const float* xrow = x + ((size_t)b * Nv + n) * Tv;
    xs[tid] = xrow[tid];
    xs[tid + 128] = xrow[tid + 128];
    __syncthreads();

    if (tid < 127) po[tid] = make_float2(xs[2 * tid + 1], xs[2 * tid + 2]);
    for (int i = tid; i < TTv; i += 128) rxs[i] = 1.0f / xs[i + Lv];

    // Weights for gates {i, g, o} (gate f is dead) straight into registers.
    float wi[Lv], wg[Lv], wo[Lv];
    {
        const float* Wn = Wih + (size_t)n * 4 * Hv * Lv;
        const float4* p0 = (const float4*)(Wn + ((size_t)0 * Hv + h) * Lv);
        const float4* p2 = (const float4*)(Wn + ((size_t)2 * Hv + h) * Lv);
        const float4* p3 = (const float4*)(Wn + ((size_t)3 * Hv + h) * Lv);
#pragma unroll
        for (int q = 0; q < 8; q++) {
            float4 v0 = p0[q], v2 = p2[q], v3 = p3[q];
            wi[4 * q] = v0.x; wi[4 * q + 1] = v0.y; wi[4 * q + 2] = v0.z; wi[4 * q + 3] = v0.w;
            wg[4 * q] = v2.x; wg[4 * q + 1] = v2.y; wg[4 * q + 2] = v2.z; wg[4 * q + 3] = v2.w;
            wo[4 * q] = v3.x; wo[4 * q + 1] = v3.y; wo[4 * q + 2] = v3.z; wo[4 * q + 3] = v3.w;
        }
    }

    const size_t bb4 = (size_t)n * 4 * Hv;
    const float bi = bih[bb4 + h]          + bhh[bb4 + h];
    const float bg = bih[bb4 + 2 * Hv + h] + bhh[bb4 + 2 * Hv + h];
    const float bo = bih[bb4 + 3 * Hv + h] + bhh[bb4 + 3 * Hv + h];
    const int nh = n * Hv + h;
    const float wsum_h = g_wsum4[nh] + g_wsum4[Nv * Hv + nh] +
                         g_wsum4[2 * Nv * Hv + nh] + g_wsum4[3 * Nv * Hv + nh];
    const float bsum_n = g_bsum[n];
    __syncthreads();

    // R[b,n] = sum_t rxs[t]
    {
        float r = 0.f;
        for (int i = tid; i < TTv; i += 128) r += rxs[i];
#pragma unroll
        for (int off = 16; off; off >>= 1) r += __shfl_xor_sync(0xffffffffu, r, off);
        if (lane == 0) redR[warp] = r;
        __syncthreads();
        if (tid == 0) g_R[b * Nv + n] = redR[0] + redR[1] + redR[2] + redR[3];
    }

    const u64t bi2 = pack2(bi, bi);
    const u64t bg2 = pack2(bg, bg);
    const u64t bo2 = pack2(bo, bo);

    float hs_acc = 0.f;

    for (int it = 0; it < TTv / 8; it++) {
        const int t0 = it * 8;     // even
        u64t ai[4], ag[4], ao[4];
#pragma unroll
        for (int p = 0; p < 4; p++) { ai[p] = bi2; ag[p] = bg2; ao[p] = bo2; }

        const u64t* peb = (const u64t*)xs + (t0 >> 1);   // even-aligned pairs
        const u64t* pob = (const u64t*)po + (t0 >> 1);   // odd-aligned pairs

#pragma unroll
        for (int l = 0; l < Lv; l++) {
            const u64t* px = (l & 1) ? (pob + ((l - 1) >> 1)) : (peb + (l >> 1));
            const u64t x0 = px[0], x1 = px[1], x2 = px[2], x3 = px[3];
            const u64t wi2 = pack2(wi[l], wi[l]);
            const u64t wg2 = pack2(wg[l], wg[l]);
            const u64t wo2 = pack2(wo[l], wo[l]);
            ai[0] = ffma2(x0, wi2, ai[0]); ai[1] = ffma2(x1, wi2, ai[1]);
            ai[2] = ffma2(x2, wi2, ai[2]); ai[3] = ffma2(x3, wi2, ai[3]);
            ag[0] = ffma2(x0, wg2, ag[0]); ag[1] = ffma2(x1, wg2, ag[1]);
            ag[2] = ffma2(x2, wg2, ag[2]); ag[3] = ffma2(x3, wg2, ag[3]);
            ao[0] = ffma2(x0, wo2, ao[0]); ao[1] = ffma2(x1, wo2, ao[1]);
            ao[2] = ffma2(x2, wo2, ao[2]); ao[3] = ffma2(x3, wo2, ao[3]);
        }

        float sx[8];
#pragma unroll
        for (int p = 0; p < 4; p++) {
            const float2 vi = unpack2(ai[p]);
            const float2 vg = unpack2(ag[p]);
            const float2 vo = unpack2(ao[p]);
            {
                const float c  = sig_fast(vi.x) * tanh_fast(vg.x);
                const float hv = sig_fast(vo.x) * tanh_fast(c);
                hs_acc = fmaf(hv, rxs[t0 + 2 * p], hs_acc);
                sx[2 * p] = hv * wsum_h;
            }
            {
                const float c  = sig_fast(vi.y) * tanh_fast(vg.y);
                const float hv = sig_fast(vo.y) * tanh_fast(c);
                hs_acc = fmaf(hv, rxs[t0 + 2 * p + 1], hs_acc);
                sx[2 * p + 1] = hv * wsum_h;
            }
        }

        // Warp-local reduce over h; lane0 stores per-warp partial. NO barrier.
#pragma unroll
        for (int tt = 0; tt < 8; tt++) {
            float v = sx[tt];
            v += __shfl_xor_sync(0xffffffffu, v, 16);
            v += __shfl_xor_sync(0xffffffffu, v, 8);
            v += __shfl_xor_sync(0xffffffffu, v, 4);
            v += __shfl_xor_sync(0xffffffffu, v, 2);
            v += __shfl_xor_sync(0xffffffffu, v, 1);
            if (lane == 0) redX[warp * TTv + t0 + tt] = v;
        }
    }

    g_hsum[((size_t)b * Nv + n) * Hv + h] = hs_acc;

    // Single barrier, then X_hat epilogue: sum 4 warp partials per t.
    __syncthreads();
    for (int i = tid; i < TTv; i += 128) {
        const float s = redX[i] + redX[TTv + i] + redX[2 * TTv + i] + redX[3 * TTv + i];
        outX[((size_t)b * TTv + i) * Nv + n] = s + bsum_n + 1e-6f;
    }
}

// ---------------------------------------------------------------------------
// K2: G[b,j,n] = (sum_h W_fc[n,j,h]*Hsum[b,n,h] + b_fc[n,j]*R[b,n]) / 224
// ---------------------------------------------------------------------------
__global__ void __launch_bounds__(256) k_gout(const float* __restrict__ Wfc,
                                              const float* __restrict__ bfc,
                                              float* __restrict__ outG) {
    const int n = blockIdx.x;
    const int tid = threadIdx.x;
    const int w = tid >> 5, lane = tid & 31;
    __shared__ __align__(16) float Hs[Bv][Hv];
    __shared__ float Rs[Bv];

    for (int i = tid; i < Bv * Hv; i += 256) {
        int bb = i >> 7, hh = i & 127;
        Hs[bb][hh] = g_hsum[((size_t)bb * Nv + n) * Hv + hh];
    }
    if (tid < Bv) Rs[tid] = g_R[tid * Nv + n];
    __syncthreads();

    float Hl[Bv][4];
#pragma unroll
    for (int bb = 0; bb < Bv; bb++) {
        float4 v = *(const float4*)&Hs[bb][4 * lane];
        Hl[bb][0] = v.x; Hl[bb][1] = v.y; Hl[bb][2] = v.z; Hl[bb][3] = v.w;
    }

    const float sc = 1.0f / (float)TTv;
#pragma unroll 2
    for (int jj = 0; jj < 16; jj++) {
        const int j = w * 16 + jj;
        const float4 wv = ((const float4*)(Wfc + ((size_t)n * Nv + j) * Hv))[lane];
        float acc[Bv];
#pragma unroll
        for (int bb = 0; bb < Bv; bb++) {
            acc[bb] = wv.x * Hl[bb][0] + wv.y * Hl[bb][1] +
                      wv.z * Hl[bb][2] + wv.w * Hl[bb][3];
        }
#pragma unroll
        for (int off = 16; off; off >>= 1) {
#pragma unroll
            for (int bb = 0; bb < Bv; bb++)
                acc[bb] += __shfl_xor_sync(0xffffffffu, acc[bb], off);
        }
        if (lane == 0) {
            const float bj = bfc[n * Nv + j];
#pragma unroll
            for (int bb = 0; bb < Bv; bb++)
                outG[((size_t)bb * Nv + j) * Nv + n] = (acc[bb] + bj * Rs[bb]) * sc;
        }
    }
}

// ---------------------------------------------------------------------------
extern "C" void kernel_launch(void* const* d_in, const int* in_sizes, int n_in,
                              void* d_out, int out_size) {
    (void)in_sizes; (void)n_in; (void)out_size;
    const float* x   = (const float*)d_in[0];
    const float* Wih = (const float*)d_in[1];
    const float* bih = (const float*)d_in[2];
    const float* bhh = (const float*)d_in[3];
    const float* Wfc = (const float*)d_in[4];
    const float* bfc = (const float*)d_in[5];

    float* outG = (float*)d_out;                       // (B, N, N)
    float* outX = outG + (size_t)Bv * Nv * Nv;         // (B, Ttau, N)

    dim3 g0(Nv, 4);
    k_prep<<<g0, 128>>>(Wfc, bfc);
    dim3 g1(Nv, Bv);
    k_lstm<<<g1, 128>>>(x, Wih, bih, bhh, outX);
    k_gout<<<Nv, 256>>>(Wfc, bfc, outG);
}